// round 4
// baseline (speedup 1.0000x reference)
#include <cuda_runtime.h>
#include <math.h>

#define BS        1048576
#define N_AGENTS  8
#define N_HEAD    4

#define HA_ELEMS   (BS * N_AGENTS)          // 8388608 floats = 32 MB
#define V_ELEMS    (BS)                     // 1048576 floats = 4 MB
#define HA_VEC4    (HA_ELEMS / 4)           // 2097152
#define V_VEC4     (V_ELEMS / 4)            // 262144
#define FILL_VEC4  (HA_VEC4 + V_VEC4)       // 2359296

#define THREADS      256
#define FILL_BLOCKS  296                    // 2 blocks/SM, one wave
// 2359296 / 296 = 7970.6 -> grid-stride loop

__global__ __launch_bounds__(THREADS)
void qatten_fused_kernel(const float* __restrict__ sel_w,
                         const float* __restrict__ key_w,
                         const float* __restrict__ V,
                         float* __restrict__ out) {
    const int bid = blockIdx.x;
    const int t   = threadIdx.x;

    if (bid < FILL_BLOCKS) {
        const float vv = V[0];
        float4* __restrict__ out4 = reinterpret_cast<float4*>(out);
        const float4 half4 = make_float4(0.5f, 0.5f, 0.5f, 0.5f);
        const float4 v4    = make_float4(vv, vv, vv, vv);

        const int stride = FILL_BLOCKS * THREADS;             // 75776
        // Streaming stores (evict-first): full pass over 2359296 float4s
        for (int idx = bid * THREADS + t; idx < FILL_VEC4; idx += stride) {
            __stcs(&out4[idx], (idx < HA_VEC4) ? half4 : v4);
        }
        return;
    }

    // ---- Tail block: scalar reg term + entropies ----
    __shared__ float warp_sums[THREADS / 32];

    const int wid = t >> 5;
    float p = sel_w[t] * key_w[t];   // sel_w/key_w are (4,64) contiguous = 256 elems

    #pragma unroll
    for (int off = 16; off > 0; off >>= 1)
        p += __shfl_down_sync(0xFFFFFFFFu, p, off);
    if ((t & 31) == 0) warp_sums[wid] = p;
    __syncthreads();

    if (t == 0) {
        float reg = 0.0f;
        #pragma unroll
        for (int h = 0; h < N_HEAD; h++) {
            float dot_h = warp_sums[2 * h] + warp_sums[2 * h + 1];
            reg += dot_h * dot_h;
        }
        out[HA_ELEMS + V_ELEMS] = 0.001f * reg;

        const float prob = 0.125f;
        const float ent  = -(8.0f * prob * logf(prob + 1e-8f));
        #pragma unroll
        for (int h = 0; h < N_HEAD; h++)
            out[HA_ELEMS + V_ELEMS + 1 + h] = ent;
    }
}

extern "C" void kernel_launch(void* const* d_in, const int* in_sizes, int n_in,
                              void* d_out, int out_size) {
    // metadata order: agent_qs(f32), actions(i64), sel_w(f32), key_w(f32), V(f32)
    const float* sel_w = (const float*)d_in[2];
    const float* key_w = (const float*)d_in[3];
    const float* V     = (const float*)d_in[4];
    float* out = (float*)d_out;

    qatten_fused_kernel<<<FILL_BLOCKS + 1, THREADS>>>(sel_w, key_w, V, out);
}

// round 5
// speedup vs baseline: 1.0238x; 1.0238x over previous
#include <cuda_runtime.h>
#include <math.h>

#define BS        1048576
#define N_AGENTS  8
#define N_HEAD    4

#define HA_ELEMS   (BS * N_AGENTS)          // 8388608 floats = 32 MB
#define V_ELEMS    (BS)                     // 1048576 floats = 4 MB
#define HA_VEC4    (HA_ELEMS / 4)           // 2097152
#define V_VEC4     (V_ELEMS / 4)            // 262144
#define FILL_VEC4  (HA_VEC4 + V_VEC4)       // 2359296

#define THREADS     256
#define UNROLL      8
#define CHUNK_VEC4  (THREADS * UNROLL)                  // 2048 float4 per block
#define FILL_BLOCKS (FILL_VEC4 / CHUNK_VEC4)            // 1152 exactly
#define HA_BLOCKS   (HA_VEC4 / CHUNK_VEC4)              // 1024 exactly

__global__ __launch_bounds__(THREADS)
void qatten_fused_kernel(const float* __restrict__ sel_w,
                         const float* __restrict__ key_w,
                         const float* __restrict__ V,
                         float* __restrict__ out) {
    const int bid = blockIdx.x;
    const int t   = threadIdx.x;

    // ---- Fill path: 8 back-to-back STG.128 per thread, value uniform per block ----
    const float v = (bid < HA_BLOCKS) ? 0.5f : V[0];
    const float4 val = make_float4(v, v, v, v);
    float4* __restrict__ base =
        reinterpret_cast<float4*>(out) + (long long)bid * CHUNK_VEC4 + t;
    #pragma unroll
    for (int i = 0; i < UNROLL; i++) {
        base[i * THREADS] = val;
    }

    // ---- Scalar tail folded into the last block (stores above are independent) ----
    if (bid == FILL_BLOCKS - 1) {
        __shared__ float warp_sums[THREADS / 32];

        const int wid = t >> 5;
        float p = sel_w[t] * key_w[t];   // sel_w/key_w are (4,64) contiguous = 256 elems

        #pragma unroll
        for (int off = 16; off > 0; off >>= 1)
            p += __shfl_down_sync(0xFFFFFFFFu, p, off);
        if ((t & 31) == 0) warp_sums[wid] = p;
        __syncthreads();

        if (t == 0) {
            float reg = 0.0f;
            #pragma unroll
            for (int h = 0; h < N_HEAD; h++) {
                float dot_h = warp_sums[2 * h] + warp_sums[2 * h + 1];
                reg += dot_h * dot_h;
            }
            out[HA_ELEMS + V_ELEMS] = 0.001f * reg;

            const float prob = 0.125f;
            const float ent  = -(8.0f * prob * logf(prob + 1e-8f));
            #pragma unroll
            for (int h = 0; h < N_HEAD; h++)
                out[HA_ELEMS + V_ELEMS + 1 + h] = ent;
        }
    }
}

extern "C" void kernel_launch(void* const* d_in, const int* in_sizes, int n_in,
                              void* d_out, int out_size) {
    // metadata order: agent_qs(f32), actions(i64), sel_w(f32), key_w(f32), V(f32)
    const float* sel_w = (const float*)d_in[2];
    const float* key_w = (const float*)d_in[3];
    const float* V     = (const float*)d_in[4];
    float* out = (float*)d_out;

    qatten_fused_kernel<<<FILL_BLOCKS, THREADS>>>(sel_w, key_w, V, out);
}

// round 6
// speedup vs baseline: 1.0552x; 1.0307x over previous
#include <cuda_runtime.h>
#include <math.h>

#define BS        1048576
#define N_AGENTS  8
#define N_HEAD    4

#define HA_ELEMS   (BS * N_AGENTS)          // 8388608 floats = 32 MB
#define V_ELEMS    (BS)                     // 1048576 floats = 4 MB
#define HA_VEC4    (HA_ELEMS / 4)           // 2097152
#define V_VEC4     (V_ELEMS / 4)            // 262144
#define FILL_VEC4  (HA_VEC4 + V_VEC4)       // 2359296

#define THREADS     256
#define FILL_BLOCKS (FILL_VEC4 / THREADS)   // 9216 exactly
#define HA_BLOCKS   (HA_VEC4 / THREADS)     // 8192 exactly (block-aligned boundary)

__global__ __launch_bounds__(THREADS)
void qatten_fused_kernel(const float* __restrict__ sel_w,
                         const float* __restrict__ key_w,
                         const float* __restrict__ V,
                         float* __restrict__ out) {
    const unsigned bid = blockIdx.x;
    const unsigned t   = threadIdx.x;

    // ---- Fill path: exactly one STG.128 per thread, value uniform per block ----
    const float v = (bid < HA_BLOCKS) ? 0.5f : V[0];
    reinterpret_cast<float4*>(out)[bid * THREADS + t] = make_float4(v, v, v, v);

    // ---- Scalar tail folded into the last block ----
    if (bid == FILL_BLOCKS - 1) {
        __shared__ float warp_sums[THREADS / 32];

        const unsigned wid = t >> 5;
        float p = sel_w[t] * key_w[t];   // sel_w/key_w are (4,64) contiguous = 256 elems

        #pragma unroll
        for (int off = 16; off > 0; off >>= 1)
            p += __shfl_down_sync(0xFFFFFFFFu, p, off);
        if ((t & 31) == 0) warp_sums[wid] = p;
        __syncthreads();

        if (t == 0) {
            float reg = 0.0f;
            #pragma unroll
            for (int h = 0; h < N_HEAD; h++) {
                float dot_h = warp_sums[2 * h] + warp_sums[2 * h + 1];
                reg += dot_h * dot_h;
            }
            out[HA_ELEMS + V_ELEMS] = 0.001f * reg;

            const float prob = 0.125f;
            const float ent  = -(8.0f * prob * logf(prob + 1e-8f));
            #pragma unroll
            for (int h = 0; h < N_HEAD; h++)
                out[HA_ELEMS + V_ELEMS + 1 + h] = ent;
        }
    }
}

extern "C" void kernel_launch(void* const* d_in, const int* in_sizes, int n_in,
                              void* d_out, int out_size) {
    // metadata order: agent_qs(f32), actions(i64), sel_w(f32), key_w(f32), V(f32)
    const float* sel_w = (const float*)d_in[2];
    const float* key_w = (const float*)d_in[3];
    const float* V     = (const float*)d_in[4];
    float* out = (float*)d_out;

    qatten_fused_kernel<<<FILL_BLOCKS, THREADS>>>(sel_w, key_w, V, out);
}